// round 9
// baseline (speedup 1.0000x reference)
#include <cuda_runtime.h>
#include <math.h>

#define B   128
#define NZ  128
#define H   512
#define V   8192
#define S   64
#define H3  1536
#define EPS_BN  1e-5f
#define EPS_COS 1e-8f
#define NEG 0.2f
#define BV  (B*V)

// ---------------- static device scratch (allocations forbidden) ------------
__device__ __align__(16) float d_z0 [B*H];
__device__ __align__(16) float d_siz[B*H];
__device__ __align__(16) float d_cz [B*H3];
__device__ __align__(16) float d_gim[S*H3];
__device__ float d_g[(size_t)S*BV];           // 256 MiB gumbel noise
__device__ __align__(16) float d_six[B*H];
__device__ __align__(16) float d_gi [B*H3];
__device__ __align__(16) float d_ghx[B*H3];
__device__ __align__(16) float d_ghm[B*H3];
__device__ __align__(16) float d_hx [B*H];
__device__ __align__(16) float d_hm [B*H];
__device__ __align__(16) float d_ohi[B*H];    // tf32-hi of bn3 output
__device__ __align__(16) float d_olo[B*H];    // tf32-lo
__device__ __align__(16) float d_whi[(size_t)V*H];  // 16 MB tf32-hi of h2o_w
__device__ __align__(16) float d_wlo[(size_t)V*H];  // 16 MB tf32-lo
__device__ float d_logits[B*V];
__device__ int   d_prev[B];
__device__ unsigned d_keys[2*S];

// ---------------- threefry2x32 (bit-exact vs JAX) --------------------------
__device__ __forceinline__ void threefry(unsigned k0, unsigned k1,
                                         unsigned c0, unsigned c1,
                                         unsigned &o0, unsigned &o1) {
  unsigned ks2 = k0 ^ k1 ^ 0x1BD11BDAu;
  unsigned x0 = c0 + k0, x1 = c1 + k1;
#define TFR(r) { x0 += x1; x1 = (x1 << (r)) | (x1 >> (32 - (r))); x1 ^= x0; }
  TFR(13) TFR(15) TFR(26) TFR(6)   x0 += k1;  x1 += ks2 + 1u;
  TFR(17) TFR(29) TFR(16) TFR(24)  x0 += ks2; x1 += k0 + 2u;
  TFR(13) TFR(15) TFR(26) TFR(6)   x0 += k0;  x1 += k1 + 3u;
  TFR(17) TFR(29) TFR(16) TFR(24)  x0 += k1;  x1 += ks2 + 4u;
  TFR(13) TFR(15) TFR(26) TFR(6)   x0 += ks2; x1 += k0 + 5u;
#undef TFR
  o0 = x0; o1 = x1;
}

__device__ __forceinline__ float gumbel_from_bits(unsigned bits) {
  float f = __uint_as_float((bits >> 9) | 0x3f800000u) - 1.0f;   // [0,1)
  float u = fmaxf(1e-6f, __fadd_rn(__fmul_rn(f, (1.0f - 1e-6f) - 1e-6f), 1e-6f));
  return -logf(-logf(u));
}

__global__ void k_keys() {
  int s = threadIdx.x;
  if (s < S) { unsigned o0,o1; threefry(0u,42u,0u,(unsigned)s,o0,o1);
               d_keys[2*s]=o0; d_keys[2*s+1]=o1; }
}

// Partitionable threefry random_bits: counter (0, i), 32-bit out = o0 ^ o1.
__global__ void k_gumbel() {
  int idx = blockIdx.x * blockDim.x + threadIdx.x;
  int s = idx / BV;
  int i = idx - s * BV;
  unsigned o0,o1;
  threefry(d_keys[2*s], d_keys[2*s+1], 0u, (unsigned)i, o0, o1);
  d_g[(size_t)s * BV + i] = gumbel_from_bits(o0 ^ o1);
}

// ---------------- helpers ---------------------------------------------------
__device__ __forceinline__ float bredsum(float v, float* sh) {
  int t = threadIdx.x;
  sh[t] = v; __syncthreads();
#pragma unroll
  for (int o = 64; o > 0; o >>= 1) { if (t < o) sh[t] += sh[t+o]; __syncthreads(); }
  float r = sh[0]; __syncthreads();
  return r;
}
__device__ __forceinline__ float leaky(float x) { return x >= 0.f ? x : NEG*x; }
__device__ __forceinline__ float sig(float x)   { return 1.f/(1.f+expf(-x)); }

__device__ __forceinline__ float tf32r(float x) {
  unsigned r; asm("cvt.rna.tf32.f32 %0, %1;" : "=r"(r) : "f"(x));
  return __uint_as_float(r);
}

#define MMA_TF32(c, a, b) \
  asm("mma.sync.aligned.m16n8k8.row.col.f32.tf32.tf32.f32 " \
      "{%0,%1,%2,%3}, {%4,%5,%6,%7}, {%8,%9}, {%0,%1,%2,%3};" \
      : "+f"((c).x), "+f"((c).y), "+f"((c).z), "+f"((c).w) \
      : "r"(__float_as_uint((a).x)), "r"(__float_as_uint((a).y)), \
        "r"(__float_as_uint((a).z)), "r"(__float_as_uint((a).w)), \
        "r"(__float_as_uint((b).x)), "r"(__float_as_uint((b).y)))

// ---------------- setup kernels ---------------------------------------------
__global__ void k_z0(const float* __restrict__ z, const float* __restrict__ w,
                     const float* __restrict__ bias, const float* __restrict__ gg,
                     const float* __restrict__ bb) {
  __shared__ float sh[128];
  int b = threadIdx.x, c0 = blockIdx.x * 4;
  const float* zr = z + b*NZ;
  for (int j = 0; j < 4; j++) {
    int col = c0 + j;
    float acc = bias[col];
    const float* wr = w + col*NZ;
    for (int k = 0; k < NZ; k++) acc = fmaf(zr[k], wr[k], acc);
    float v   = leaky(acc);
    float mu  = bredsum(v, sh) * (1.f/B);
    float dd  = v - mu;
    float var = bredsum(dd*dd, sh) * (1.f/B);
    d_z0[b*H + col] = gg[col]*dd*rsqrtf(var + EPS_BN) + bb[col];
  }
}

__global__ void k_prep() {
  int i = blockIdx.x * blockDim.x + threadIdx.x;
  if (i < B*H) { float v = d_z0[i]; d_hx[i] = v; d_hm[i] = v; }
  if (i < B) d_prev[i] = V - 1;
}

// one-time: split h2o_w into tf32 hi/lo
__global__ void k_wsplit(const float* __restrict__ w) {
  size_t i = (size_t)blockIdx.x * blockDim.x + threadIdx.x;
  float x  = w[i];
  float hi = tf32r(x);
  d_whi[i] = hi;
  d_wlo[i] = tf32r(x - hi);
}

__global__ void k_siz(const float* __restrict__ g2, const float* __restrict__ b2) {
  __shared__ float sh[128];
  int b = threadIdx.x, c0 = blockIdx.x * 4;
  for (int j = 0; j < 4; j++) {
    int col = c0 + j;
    float v   = d_z0[b*H + col];
    float mu  = bredsum(v, sh) * (1.f/B);
    float dd  = v - mu;
    float var = bredsum(dd*dd, sh) * (1.f/B);
    d_siz[b*H + col] = g2[H+col]*dd*rsqrtf(var + EPS_BN) + b2[H+col];
  }
}

__global__ void k_gim(const float* __restrict__ mem, const float* __restrict__ W,
                      const float* __restrict__ bias) {
  __shared__ float a[2*H];
  int s = blockIdx.x;
  for (int k = threadIdx.x; k < 2*H; k += 256) a[k] = mem[(size_t)s*2*H + k];
  __syncthreads();
  for (int n = threadIdx.x; n < H3; n += 256) {
    float acc = bias[n];
    const float* w = W + (size_t)n*2*H;
    for (int k = 0; k < 2*H; k++) acc = fmaf(a[k], w[k], acc);
    d_gim[s*H3 + n] = acc;
  }
}

__global__ void k_embbn(const float* __restrict__ emb,
                        const float* __restrict__ g2, const float* __restrict__ b2) {
  __shared__ float sh[128];
  int b = threadIdx.x, c0 = blockIdx.x * 4;
  const float* er = emb + (size_t)d_prev[b]*H;
  for (int j = 0; j < 4; j++) {
    int col = c0 + j;
    float e   = leaky(er[col]);
    float mu  = bredsum(e, sh) * (1.f/B);
    float dd  = e - mu;
    float var = bredsum(dd*dd, sh) * (1.f/B);
    d_six[b*H + col] = g2[col]*dd*rsqrtf(var + EPS_BN) + b2[col];
  }
}

// ---------------- scalar GEMM core (R7 form) for the GRU gemms ---------------
template <int RPT>
__device__ __forceinline__ void gemm_core(
    const float* __restrict__ A, const float* __restrict__ W, int ldw,
    const float* __restrict__ bias, const float* __restrict__ addM, int ldadd,
    float* __restrict__ C, int ldc, int n0) {
  constexpr int NT = 8 * RPT;
  constexpr int TX = NT / 4;
  constexpr int WF = (NT * 8) / 256;
  __shared__ __align__(16) float Ash[32][132];
  __shared__ __align__(16) float Wsh[32][NT + 4];
  int tid = threadIdx.x;
  int tx = tid % TX, ty = tid / TX;
  int r0 = ty * RPT, c0 = tx * 4;
  float acc[RPT][4];
#pragma unroll
  for (int j = 0; j < RPT; j++)
#pragma unroll
    for (int c = 0; c < 4; c++) acc[j][c] = 0.f;

  float4 aR[4], wR[WF];
#pragma unroll
  for (int i = 0; i < 4; i++) {
    int e = tid + i*256; int row = e >> 3, kq = e & 7;
    aR[i] = *(const float4*)(A + row*512 + kq*4);
  }
#pragma unroll
  for (int i = 0; i < WF; i++) {
    int e = tid + i*256; int wr = e >> 3, kq = e & 7;
    wR[i] = *(const float4*)(W + (size_t)(n0+wr)*ldw + kq*4);
  }

  for (int it = 0; it < 16; it++) {
#pragma unroll
    for (int i = 0; i < 4; i++) {
      int e = tid + i*256; int row = e >> 3, kq = e & 7;
      Ash[kq*4+0][row] = aR[i].x; Ash[kq*4+1][row] = aR[i].y;
      Ash[kq*4+2][row] = aR[i].z; Ash[kq*4+3][row] = aR[i].w;
    }
#pragma unroll
    for (int i = 0; i < WF; i++) {
      int e = tid + i*256; int wr = e >> 3, kq = e & 7;
      Wsh[kq*4+0][wr] = wR[i].x; Wsh[kq*4+1][wr] = wR[i].y;
      Wsh[kq*4+2][wr] = wR[i].z; Wsh[kq*4+3][wr] = wR[i].w;
    }
    __syncthreads();
    if (it < 15) {
      int kt = (it+1) * 32;
#pragma unroll
      for (int i = 0; i < 4; i++) {
        int e = tid + i*256; int row = e >> 3, kq = e & 7;
        aR[i] = *(const float4*)(A + row*512 + kt + kq*4);
      }
#pragma unroll
      for (int i = 0; i < WF; i++) {
        int e = tid + i*256; int wr = e >> 3, kq = e & 7;
        wR[i] = *(const float4*)(W + (size_t)(n0+wr)*ldw + kt + kq*4);
      }
    }
#pragma unroll
    for (int kk = 0; kk < 32; kk++) {
      float av[RPT];
#pragma unroll
      for (int q = 0; q < RPT/4; q++) {
        float4 aa = *(const float4*)&Ash[kk][r0 + q*4];
        av[q*4+0]=aa.x; av[q*4+1]=aa.y; av[q*4+2]=aa.z; av[q*4+3]=aa.w;
      }
      float4 ww = *(const float4*)&Wsh[kk][c0];
      float wv4[4] = {ww.x, ww.y, ww.z, ww.w};
#pragma unroll
      for (int j = 0; j < RPT; j++)
#pragma unroll
        for (int c = 0; c < 4; c++)
          acc[j][c] = fmaf(av[j], wv4[c], acc[j][c]);
    }
    __syncthreads();
  }
#pragma unroll
  for (int j = 0; j < RPT; j++) {
    int row = r0 + j;
#pragma unroll
    for (int c = 0; c < 4; c++) {
      int col = n0 + c0 + c;
      float v = acc[j][c];
      if (bias)  v += bias[col];
      if (addM)  v += addM[(size_t)row*ldadd + col];
      C[(size_t)row*ldc + col] = v;
    }
  }
}

__global__ void __launch_bounds__(256) k_cz(const float* __restrict__ W,
                                            const float* __restrict__ bias) {
  gemm_core<4>(d_siz, W + H, 2*H, bias, (const float*)0, 0, d_cz, H3, blockIdx.x*32);
}

__global__ void __launch_bounds__(256) k_gemm3(
    const float* __restrict__ wih_x, const float* __restrict__ whh_x,
    const float* __restrict__ whh_m, const float* __restrict__ bhh_x,
    const float* __restrict__ bhh_m) {
  int n0 = blockIdx.x * 32;
  int z = blockIdx.z;
  const float* A    = (z==0) ? d_six : (z==1) ? d_hx : d_hm;
  const float* W    = (z==0) ? wih_x : (z==1) ? whh_x : whh_m;
  int ldw           = (z==0) ? 2*H : H;
  const float* bias = (z==0) ? (const float*)0 : (z==1) ? bhh_x : bhh_m;
  const float* addM = (z==0) ? d_cz : (const float*)0;
  float* Cm         = (z==0) ? d_gi : (z==1) ? d_ghx : d_ghm;
  gemm_core<4>(A, W, ldw, bias, addM, H3, Cm, H3, n0);
}

// ---------------- 3xTF32 mma.sync logits GEMM --------------------------------
// C[128, n0:n0+64] = (Ahi+Alo)[128,512] @ (Whi+Wlo)^T, 3 products (hh, lh, hl).
// 256 thr = 8 warps as 4(M)x2(N); warp tile 32x32 = 2 m-atoms x 4 n-atoms.
// Smem holds fragments pre-permuted into mma register order.
__global__ void __launch_bounds__(256) k_logits(
    int s, const float* __restrict__ bias, const float* __restrict__ tptr) {
  extern __shared__ __align__(16) float smp[];
  float* aHi = smp;              // [8 m_atoms][4 ks][32 lanes] float4 = 4096 f
  float* aLo = smp + 4096;
  float* bHi = smp + 8192;       // [8 n_atoms][4 ks][32 lanes] float2 = 2048 f
  float* bLo = smp + 10240;
  int tid  = threadIdx.x;
  int lane = tid & 31, wid = tid >> 5;
  int wm = wid >> 1, wn = wid & 1;         // warp 4(M) x 2(N)
  int n0 = blockIdx.x * 64;

  float4 acc[2][4];
#pragma unroll
  for (int mi = 0; mi < 2; mi++)
#pragma unroll
    for (int ni = 0; ni < 4; ni++) acc[mi][ni] = make_float4(0.f,0.f,0.f,0.f);

  float4 aRh[2], aRl[2], wRh[1], wRl[1];
  // stage chunk 0: A rows 128 x 32k -> 1024 f4 per version; 256 thr x... 
  // A: each thread 2 f4/version (e = tid + i*256, i<2 would cover 512)... need 4.
  // Use i<4 over 1024 f4: e in [0,1024): row = e>>3, k4 = e&7.
  float4 aRh2[2], aRl2[2];   // second pair
#define LD_A(dsth, dstl, idx, ktv) { \
    int e = tid + (idx)*256; int row = e >> 3, kq = e & 7; \
    dsth = *(const float4*)(d_ohi + row*512 + (ktv) + kq*4); \
    dstl = *(const float4*)(d_olo + row*512 + (ktv) + kq*4); }
#define LD_W(dsth, dstl, ktv) { \
    int e = tid; int wr = e >> 3, kq = e & 7; \
    dsth = *(const float4*)(d_whi + (size_t)(n0+wr)*512 + (ktv) + kq*4); \
    dstl = *(const float4*)(d_wlo + (size_t)(n0+wr)*512 + (ktv) + kq*4); }
#define ST_A(srch, srcl, idx) { \
    int e = tid + (idx)*256; int row = e >> 3, kq = e & 7; \
    int m_atom = row >> 4, m = row & 15; \
    float vh[4] = {srch.x, srch.y, srch.z, srch.w}; \
    float vl[4] = {srcl.x, srcl.y, srcl.z, srcl.w}; \
    _Pragma("unroll") \
    for (int j = 0; j < 4; j++) { \
      int kl = kq*4 + j; int ks = kl >> 3, kk = kl & 7; \
      int L = (m & 7)*4 + (kk & 3); int reg = (m >> 3) + 2*(kk >> 2); \
      int ad = ((m_atom*4 + ks)*32 + L)*4 + reg; \
      aHi[ad] = vh[j]; aLo[ad] = vl[j]; } }
#define ST_W(srch, srcl) { \
    int e = tid; int wr = e >> 3, kq = e & 7; \
    int n_atom = wr >> 3, nn = wr & 7; \
    float vh[4] = {srch.x, srch.y, srch.z, srch.w}; \
    float vl[4] = {srcl.x, srcl.y, srcl.z, srcl.w}; \
    _Pragma("unroll") \
    for (int j = 0; j < 4; j++) { \
      int kl = kq*4 + j; int ks = kl >> 3, kk = kl & 7; \
      int L = nn*4 + (kk & 3); int reg = kk >> 2; \
      int ad = ((n_atom*4 + ks)*32 + L)*2 + reg; \
      bHi[ad] = vh[j]; bLo[ad] = vl[j]; } }

  // W: 64 rows x 32k = 512 f4 per version -> 2 per thread... tid covers 256;
  // need e in [0,512): handle with two regs.
  float4 wRh2, wRl2;
#define LD_W2(dsth, dstl, ktv) { \
    int e = tid + 256; int wr = e >> 3, kq = e & 7; \
    dsth = *(const float4*)(d_whi + (size_t)(n0+wr)*512 + (ktv) + kq*4); \
    dstl = *(const float4*)(d_wlo + (size_t)(n0+wr)*512 + (ktv) + kq*4); }
#define ST_W2(srch, srcl) { \
    int e = tid + 256; int wr = e >> 3, kq = e & 7; \
    int n_atom = wr >> 3, nn = wr & 7; \
    float vh[4] = {srch.x, srch.y, srch.z, srch.w}; \
    float vl[4] = {srcl.x, srcl.y, srcl.z, srcl.w}; \
    _Pragma("unroll") \
    for (int j = 0; j < 4; j++) { \
      int kl = kq*4 + j; int ks = kl >> 3, kk = kl & 7; \
      int L = nn*4 + (kk & 3); int reg = kk >> 2; \
      int ad = ((n_atom*4 + ks)*32 + L)*2 + reg; \
      bHi[ad] = vh[j]; bLo[ad] = vl[j]; } }

  LD_A(aRh[0], aRl[0], 0, 0) LD_A(aRh[1], aRl[1], 1, 0)
  LD_A(aRh2[0], aRl2[0], 2, 0) LD_A(aRh2[1], aRl2[1], 3, 0)
  LD_W(wRh[0], wRl[0], 0) LD_W2(wRh2, wRl2, 0)

  for (int it = 0; it < 16; it++) {
    ST_A(aRh[0], aRl[0], 0) ST_A(aRh[1], aRl[1], 1)
    ST_A(aRh2[0], aRl2[0], 2) ST_A(aRh2[1], aRl2[1], 3)
    ST_W(wRh[0], wRl[0]) ST_W2(wRh2, wRl2)
    __syncthreads();
    if (it < 15) {
      int kt = (it+1) * 32;
      LD_A(aRh[0], aRl[0], 0, kt) LD_A(aRh[1], aRl[1], 1, kt)
      LD_A(aRh2[0], aRl2[0], 2, kt) LD_A(aRh2[1], aRl2[1], 3, kt)
      LD_W(wRh[0], wRl[0], kt) LD_W2(wRh2, wRl2, kt)
    }
#pragma unroll
    for (int ks = 0; ks < 4; ks++) {
      float4 ah[2], al[2];
#pragma unroll
      for (int mi = 0; mi < 2; mi++) {
        int ma = wm*2 + mi;
        ah[mi] = *(const float4*)(aHi + ((ma*4 + ks)*32 + lane)*4);
        al[mi] = *(const float4*)(aLo + ((ma*4 + ks)*32 + lane)*4);
      }
#pragma unroll
      for (int ni = 0; ni < 4; ni++) {
        int na = wn*4 + ni;
        float2 bh = *(const float2*)(bHi + ((na*4 + ks)*32 + lane)*2);
        float2 bl = *(const float2*)(bLo + ((na*4 + ks)*32 + lane)*2);
#pragma unroll
        for (int mi = 0; mi < 2; mi++) {
          MMA_TF32(acc[mi][ni], ah[mi], bh);
          MMA_TF32(acc[mi][ni], al[mi], bh);
          MMA_TF32(acc[mi][ni], ah[mi], bl);
        }
      }
    }
    __syncthreads();
  }

  // epilogue: (acc + bias + gumbel) / t
  float t = *tptr;
  const float* gb = d_g + (size_t)s*BV;
#pragma unroll
  for (int mi = 0; mi < 2; mi++) {
    int ma = wm*2 + mi;
    int row0 = ma*16 + (lane >> 2);
#pragma unroll
    for (int ni = 0; ni < 4; ni++) {
      int col0 = n0 + wn*32 + ni*8 + 2*(lane & 3);
      float bv0 = bias[col0], bv1 = bias[col0+1];
      float4 c = acc[mi][ni];
      d_logits[(size_t)row0*V + col0]       = (c.x + bv0 + gb[(size_t)row0*V + col0]) / t;
      d_logits[(size_t)row0*V + col0+1]     = (c.y + bv1 + gb[(size_t)row0*V + col0+1]) / t;
      d_logits[(size_t)(row0+8)*V + col0]   = (c.z + bv0 + gb[(size_t)(row0+8)*V + col0]) / t;
      d_logits[(size_t)(row0+8)*V + col0+1] = (c.w + bv1 + gb[(size_t)(row0+8)*V + col0+1]) / t;
    }
  }
}

// ---------------- per-step: GRU combine + cosine gate + bn3 + tf32 split -----
__global__ void k_gru(int s, const float* __restrict__ g3, const float* __restrict__ b3) {
  __shared__ float sh[128];
  int b = threadIdx.x, c0 = blockIdx.x * 4;
  const float* gim = d_gim + s*H3;
  float hx2[4], hm2[4];
#pragma unroll
  for (int j = 0; j < 4; j++) {
    int col = c0 + j;
    float ir = d_gi [b*H3+col], iz = d_gi [b*H3+H+col], in_ = d_gi [b*H3+2*H+col];
    float hr = d_ghx[b*H3+col], hz = d_ghx[b*H3+H+col], hn  = d_ghx[b*H3+2*H+col];
    float h  = d_hx[b*H+col];
    float r  = sig(ir+hr), zg = sig(iz+hz);
    float n  = tanhf(in_ + r*hn);
    hx2[j] = (1.f-zg)*n + zg*h;
    float mir = gim[col], miz = gim[H+col], min_ = gim[2*H+col];
    float mhr = d_ghm[b*H3+col], mhz = d_ghm[b*H3+H+col], mhn = d_ghm[b*H3+2*H+col];
    float hmv = d_hm[b*H+col];
    float rm  = sig(mir+mhr), zm = sig(miz+mhz);
    float nm  = tanhf(min_ + rm*mhn);
    hm2[j] = (1.f-zm)*nm + zm*hmv;
    d_hx[b*H+col] = hx2[j];
    d_hm[b*H+col] = hm2[j];
  }
  float dot=0.f, na=0.f, nb=0.f;
#pragma unroll
  for (int j = 0; j < 4; j++) { dot += hx2[j]*hm2[j]; na += hx2[j]*hx2[j]; nb += hm2[j]*hm2[j]; }
  float gate = dot / fmaxf(sqrtf(na)*sqrtf(nb), EPS_COS);
#pragma unroll
  for (int j = 0; j < 4; j++) {
    int col = c0 + j;
    float o   = leaky(gate*hx2[j] + (1.f-gate)*hm2[j]);
    float mu  = bredsum(o, sh) * (1.f/B);
    float dd  = o - mu;
    float var = bredsum(dd*dd, sh) * (1.f/B);
    float ov  = g3[col]*dd*rsqrtf(var + EPS_BN) + b3[col];
    float hi  = tf32r(ov);
    d_ohi[b*H+col] = hi;
    d_olo[b*H+col] = tf32r(ov - hi);
  }
}

// ---------------- per-step: softmax + argmax + write probs -------------------
__global__ void __launch_bounds__(512) k_smax(int s, float* __restrict__ out) {
  __shared__ float se[V];
  __shared__ float sh[512];
  __shared__ int   shi[512];
  int b = blockIdx.x, t = threadIdx.x;
  const float* row = d_logits + (size_t)b*V;
  float m = -3.0e38f;
  for (int v = t; v < V; v += 512) m = fmaxf(m, row[v]);
  sh[t] = m; __syncthreads();
#pragma unroll
  for (int o = 256; o > 0; o >>= 1) { if (t < o) sh[t] = fmaxf(sh[t], sh[t+o]); __syncthreads(); }
  m = sh[0]; __syncthreads();
  float sum = 0.f;
  for (int v = t; v < V; v += 512) { float e = expf(row[v]-m); se[v] = e; sum += e; }
  sh[t] = sum; __syncthreads();
#pragma unroll
  for (int o = 256; o > 0; o >>= 1) { if (t < o) sh[t] += sh[t+o]; __syncthreads(); }
  sum = sh[0]; __syncthreads();
  float best = -1.f; int bi = 0;
  float* orow = out + (size_t)b*S*V + (size_t)s*V;
  for (int v = t; v < V; v += 512) {
    float p = se[v] / sum;
    orow[v] = p;
    if (p > best) { best = p; bi = v; }
  }
  sh[t] = best; shi[t] = bi; __syncthreads();
#pragma unroll
  for (int o = 256; o > 0; o >>= 1) {
    if (t < o) {
      float ov = sh[t+o]; int oi = shi[t+o];
      if (ov > sh[t] || (ov == sh[t] && oi < shi[t])) { sh[t] = ov; shi[t] = oi; }
    }
    __syncthreads();
  }
  if (t == 0) d_prev[b] = shi[0];
}

#define SMEM_LG (12288 * 4)   // 49152 B fragment smem

// ---------------- launch ------------------------------------------------------
extern "C" void kernel_launch(void* const* d_in, const int* in_sizes, int n_in,
                              void* d_out, int out_size) {
  const float* z      = (const float*)d_in[0];
  const float* temp   = (const float*)d_in[1];
  const float* z2h_w  = (const float*)d_in[2];
  const float* z2h_b  = (const float*)d_in[3];
  const float* bn1_g  = (const float*)d_in[4];
  const float* bn1_b  = (const float*)d_in[5];
  const float* emb    = (const float*)d_in[6];
  const float* bn2_g  = (const float*)d_in[7];
  const float* bn2_b  = (const float*)d_in[8];
  const float* memory = (const float*)d_in[9];
  const float* gx_wih = (const float*)d_in[10];
  const float* gx_whh = (const float*)d_in[11];
  const float* gx_bih = (const float*)d_in[12];
  const float* gx_bhh = (const float*)d_in[13];
  const float* gm_wih = (const float*)d_in[14];
  const float* gm_whh = (const float*)d_in[15];
  const float* gm_bih = (const float*)d_in[16];
  const float* gm_bhh = (const float*)d_in[17];
  const float* bn3_g  = (const float*)d_in[18];
  const float* bn3_b  = (const float*)d_in[19];
  const float* h2o_w  = (const float*)d_in[20];
  const float* h2o_b  = (const float*)d_in[21];
  float* out = (float*)d_out;

  static int smem_set = 0;
  if (!smem_set) {
    cudaFuncSetAttribute(k_logits, cudaFuncAttributeMaxDynamicSharedMemorySize, SMEM_LG);
    smem_set = 1;
  }

  k_keys   <<<1, 64>>>();
  k_gumbel <<<(S*(size_t)BV)/256, 256>>>();
  k_z0     <<<128, 128>>>(z, z2h_w, z2h_b, bn1_g, bn1_b);
  k_prep   <<<256, 256>>>();
  k_wsplit <<<(V*H)/256, 256>>>(h2o_w);
  k_siz    <<<128, 128>>>(bn2_g, bn2_b);
  k_cz     <<<48, 256>>>(gx_wih, gx_bih);
  k_gim    <<<S, 256>>>(memory, gm_wih, gm_bih);

  for (int s = 0; s < S; s++) {
    k_embbn <<<128, 128>>>(emb, bn2_g, bn2_b);
    k_gemm3 <<<dim3(48,1,3), 256>>>(gx_wih, gx_whh, gm_whh, gx_bhh, gm_bhh);
    k_gru   <<<128, 128>>>(s, bn3_g, bn3_b);
    k_logits<<<128, 256, SMEM_LG>>>(s, h2o_b, temp);
    k_smax  <<<128, 512>>>(s, out);
  }
}

// round 11
// speedup vs baseline: 1.0745x; 1.0745x over previous
#include <cuda_runtime.h>
#include <math.h>

#define B   128
#define NZ  128
#define H   512
#define V   8192
#define S   64
#define H3  1536
#define EPS_BN  1e-5f
#define EPS_COS 1e-8f
#define NEG 0.2f
#define BV  (B*V)
#define NB  144        // persistent grid size (<=148 SMs, 1 block/SM resident)

// ---------------- static device scratch (allocations forbidden) ------------
__device__ __align__(16) float d_z0 [B*H];
__device__ __align__(16) float d_siz[B*H];
__device__ __align__(16) float d_cz [B*H3];
__device__ __align__(16) float d_gim[S*H3];
__device__ float d_g[(size_t)S*BV];           // 256 MiB gumbel noise
__device__ __align__(16) float d_six[B*H];
__device__ __align__(16) float d_gi [B*H3];
__device__ __align__(16) float d_ghx[B*H3];
__device__ __align__(16) float d_ghm[B*H3];
__device__ __align__(16) float d_hx [B*H];
__device__ __align__(16) float d_hm [B*H];
__device__ __align__(16) float d_o  [B*H];
__device__ float d_logits[B*V];
__device__ int   d_prev[B];
__device__ unsigned d_keys[2*S];
__device__ unsigned g_cnt;
__device__ volatile unsigned g_gen;

// ---------------- threefry2x32 (bit-exact vs JAX) --------------------------
__device__ __forceinline__ void threefry(unsigned k0, unsigned k1,
                                         unsigned c0, unsigned c1,
                                         unsigned &o0, unsigned &o1) {
  unsigned ks2 = k0 ^ k1 ^ 0x1BD11BDAu;
  unsigned x0 = c0 + k0, x1 = c1 + k1;
#define TFR(r) { x0 += x1; x1 = (x1 << (r)) | (x1 >> (32 - (r))); x1 ^= x0; }
  TFR(13) TFR(15) TFR(26) TFR(6)   x0 += k1;  x1 += ks2 + 1u;
  TFR(17) TFR(29) TFR(16) TFR(24)  x0 += ks2; x1 += k0 + 2u;
  TFR(13) TFR(15) TFR(26) TFR(6)   x0 += k0;  x1 += k1 + 3u;
  TFR(17) TFR(29) TFR(16) TFR(24)  x0 += k1;  x1 += ks2 + 4u;
  TFR(13) TFR(15) TFR(26) TFR(6)   x0 += ks2; x1 += k0 + 5u;
#undef TFR
  o0 = x0; o1 = x1;
}

__device__ __forceinline__ float gumbel_from_bits(unsigned bits) {
  float f = __uint_as_float((bits >> 9) | 0x3f800000u) - 1.0f;   // [0,1)
  float u = fmaxf(1e-6f, __fadd_rn(__fmul_rn(f, (1.0f - 1e-6f) - 1e-6f), 1e-6f));
  return -logf(-logf(u));
}

__global__ void k_keys() {
  int s = threadIdx.x;
  if (s < S) { unsigned o0,o1; threefry(0u,42u,0u,(unsigned)s,o0,o1);
               d_keys[2*s]=o0; d_keys[2*s+1]=o1; }
}

// Partitionable threefry random_bits: counter (0, i), 32-bit out = o0 ^ o1.
__global__ void k_gumbel() {
  int idx = blockIdx.x * blockDim.x + threadIdx.x;
  int s = idx / BV;
  int i = idx - s * BV;
  unsigned o0,o1;
  threefry(d_keys[2*s], d_keys[2*s+1], 0u, (unsigned)i, o0, o1);
  d_g[(size_t)s * BV + i] = gumbel_from_bits(o0 ^ o1);
}

// ---------------- helpers ---------------------------------------------------
__device__ __forceinline__ float bredsum(float v, float* sh) {
  int t = threadIdx.x;
  sh[t] = v; __syncthreads();
#pragma unroll
  for (int o = 64; o > 0; o >>= 1) { if (t < o) sh[t] += sh[t+o]; __syncthreads(); }
  float r = sh[0]; __syncthreads();
  return r;
}
// 128-thread (half-block) reduction inside a 256-thread block; same tree shape
// as bredsum (values bit-identical per half).
__device__ __forceinline__ float bredsum128(float v, float* sh, int t) {
  sh[t] = v; __syncthreads();
#pragma unroll
  for (int o = 64; o > 0; o >>= 1) { if (t < o) sh[t] += sh[t+o]; __syncthreads(); }
  float r = sh[0]; __syncthreads();
  return r;
}
__device__ __forceinline__ float leaky(float x) { return x >= 0.f ? x : NEG*x; }
__device__ __forceinline__ float sig(float x)   { return 1.f/(1.f+expf(-x)); }

// software grid barrier: all NB blocks resident (1/SM), deterministic.
__device__ __forceinline__ void gsync() {
  __syncthreads();
  __threadfence();
  if (threadIdx.x == 0) {
    unsigned gen = g_gen;
    if (atomicAdd(&g_cnt, 1u) == NB - 1) {
      g_cnt = 0;
      __threadfence();
      atomicExch((unsigned*)&g_gen, gen + 1u);
    } else {
      while (g_gen == gen) __nanosleep(32);
    }
  }
  __syncthreads();
  __threadfence();
}

// ---------------- setup kernels ---------------------------------------------
__global__ void k_z0(const float* __restrict__ z, const float* __restrict__ w,
                     const float* __restrict__ bias, const float* __restrict__ gg,
                     const float* __restrict__ bb) {
  __shared__ float sh[128];
  int b = threadIdx.x, c0 = blockIdx.x * 4;
  const float* zr = z + b*NZ;
  for (int j = 0; j < 4; j++) {
    int col = c0 + j;
    float acc = bias[col];
    const float* wr = w + col*NZ;
    for (int k = 0; k < NZ; k++) acc = fmaf(zr[k], wr[k], acc);
    float v   = leaky(acc);
    float mu  = bredsum(v, sh) * (1.f/B);
    float dd  = v - mu;
    float var = bredsum(dd*dd, sh) * (1.f/B);
    d_z0[b*H + col] = gg[col]*dd*rsqrtf(var + EPS_BN) + bb[col];
  }
}

__global__ void k_prep() {
  int i = blockIdx.x * blockDim.x + threadIdx.x;
  if (i < B*H) { float v = d_z0[i]; d_hx[i] = v; d_hm[i] = v; }
  if (i < B) d_prev[i] = V - 1;
  if (i == 0) { g_cnt = 0; g_gen = 0; }
}

__global__ void k_siz(const float* __restrict__ g2, const float* __restrict__ b2) {
  __shared__ float sh[128];
  int b = threadIdx.x, c0 = blockIdx.x * 4;
  for (int j = 0; j < 4; j++) {
    int col = c0 + j;
    float v   = d_z0[b*H + col];
    float mu  = bredsum(v, sh) * (1.f/B);
    float dd  = v - mu;
    float var = bredsum(dd*dd, sh) * (1.f/B);
    d_siz[b*H + col] = g2[H+col]*dd*rsqrtf(var + EPS_BN) + b2[H+col];
  }
}

__global__ void k_gim(const float* __restrict__ mem, const float* __restrict__ W,
                      const float* __restrict__ bias) {
  __shared__ float a[2*H];
  int s = blockIdx.x;
  for (int k = threadIdx.x; k < 2*H; k += 256) a[k] = mem[(size_t)s*2*H + k];
  __syncthreads();
  for (int n = threadIdx.x; n < H3; n += 256) {
    float acc = bias[n];
    const float* w = W + (size_t)n*2*H;
    for (int k = 0; k < 2*H; k++) acc = fmaf(a[k], w[k], acc);
    d_gim[s*H3 + n] = acc;
  }
}

// ---------------- scalar GEMM phase (R7 core, smem via pointer) -------------
// C[128, n0:n0+8*RPT] = A[128,512] @ W^T (+bias)(+addM)((+g)/t); 256 threads.
template <int RPT>
__device__ __forceinline__ void gemm_phase(
    const float* __restrict__ A, const float* __restrict__ W, int ldw,
    const float* bias, const float* addM, int ldadd,
    float* C, int ldc, int n0,
    const float* gbase, float t, char* smu) {
  constexpr int NT = 8 * RPT;
  constexpr int TX = NT / 4;
  constexpr int WF = (NT * 8) / 256;
  float (*Ash)[132]    = (float(*)[132])smu;
  float (*Wsh)[NT + 4] = (float(*)[NT + 4])(smu + 32*132*4);
  int tid = threadIdx.x;
  int tx = tid % TX, ty = tid / TX;
  int r0 = ty * RPT, c0 = tx * 4;
  float acc[RPT][4];
#pragma unroll
  for (int j = 0; j < RPT; j++)
#pragma unroll
    for (int c = 0; c < 4; c++) acc[j][c] = 0.f;

  float4 aR[4], wR[WF];
#pragma unroll
  for (int i = 0; i < 4; i++) {
    int e = tid + i*256; int row = e >> 3, kq = e & 7;
    aR[i] = *(const float4*)(A + row*512 + kq*4);
  }
#pragma unroll
  for (int i = 0; i < WF; i++) {
    int e = tid + i*256; int wr = e >> 3, kq = e & 7;
    wR[i] = *(const float4*)(W + (size_t)(n0+wr)*ldw + kq*4);
  }

  for (int it = 0; it < 16; it++) {
#pragma unroll
    for (int i = 0; i < 4; i++) {
      int e = tid + i*256; int row = e >> 3, kq = e & 7;
      Ash[kq*4+0][row] = aR[i].x; Ash[kq*4+1][row] = aR[i].y;
      Ash[kq*4+2][row] = aR[i].z; Ash[kq*4+3][row] = aR[i].w;
    }
#pragma unroll
    for (int i = 0; i < WF; i++) {
      int e = tid + i*256; int wr = e >> 3, kq = e & 7;
      Wsh[kq*4+0][wr] = wR[i].x; Wsh[kq*4+1][wr] = wR[i].y;
      Wsh[kq*4+2][wr] = wR[i].z; Wsh[kq*4+3][wr] = wR[i].w;
    }
    __syncthreads();
    if (it < 15) {
      int kt = (it+1) * 32;
#pragma unroll
      for (int i = 0; i < 4; i++) {
        int e = tid + i*256; int row = e >> 3, kq = e & 7;
        aR[i] = *(const float4*)(A + row*512 + kt + kq*4);
      }
#pragma unroll
      for (int i = 0; i < WF; i++) {
        int e = tid + i*256; int wr = e >> 3, kq = e & 7;
        wR[i] = *(const float4*)(W + (size_t)(n0+wr)*ldw + kt + kq*4);
      }
    }
#pragma unroll
    for (int kk = 0; kk < 32; kk++) {
      float av[RPT];
#pragma unroll
      for (int q = 0; q < RPT/4; q++) {
        float4 aa = *(const float4*)&Ash[kk][r0 + q*4];
        av[q*4+0]=aa.x; av[q*4+1]=aa.y; av[q*4+2]=aa.z; av[q*4+3]=aa.w;
      }
      float4 ww = *(const float4*)&Wsh[kk][c0];
      float wv4[4] = {ww.x, ww.y, ww.z, ww.w};
#pragma unroll
      for (int j = 0; j < RPT; j++)
#pragma unroll
        for (int c = 0; c < 4; c++)
          acc[j][c] = fmaf(av[j], wv4[c], acc[j][c]);
    }
    __syncthreads();
  }
#pragma unroll
  for (int j = 0; j < RPT; j++) {
    int row = r0 + j;
#pragma unroll
    for (int c = 0; c < 4; c++) {
      int col = n0 + c0 + c;
      float v = acc[j][c];
      if (bias)  v += bias[col];
      if (addM)  v += addM[(size_t)row*ldadd + col];
      if (gbase) v = (v + gbase[(size_t)row*V + col]) / t;
      C[(size_t)row*ldc + col] = v;
    }
  }
}

__global__ void __launch_bounds__(256) k_cz(const float* __restrict__ W,
                                            const float* __restrict__ bias) {
  __shared__ __align__(16) char sm_cz[32*132*4 + 32*36*4];
  gemm_phase<4>(d_siz, W + H, 2*H, bias, (const float*)0, 0,
                d_cz, H3, blockIdx.x*32, (const float*)0, 1.f, sm_cz);
}

// ---------------- persistent 64-step loop kernel -----------------------------
__global__ void __launch_bounds__(256) k_steps(
    const float* __restrict__ emb,
    const float* __restrict__ bn2g, const float* __restrict__ bn2b,
    const float* __restrict__ gx_wih, const float* __restrict__ gx_whh,
    const float* __restrict__ gm_whh, const float* __restrict__ gx_bhh,
    const float* __restrict__ gm_bhh,
    const float* __restrict__ bn3g, const float* __restrict__ bn3b,
    const float* __restrict__ h2o_w, const float* __restrict__ h2o_b,
    const float* __restrict__ tptr, float* __restrict__ out) {
  __shared__ __align__(16) char smu[34816];   // max(gemm8 25600, smax 34816)
  int bid = blockIdx.x, tid = threadIdx.x;
  float t = *tptr;

  for (int s = 0; s < S; s++) {
    // ---- phase 1: embedding gather + bn2 (64 blocks, 8 cols each) ----
    if (bid < 64) {
      int h = tid >> 7, bt = tid & 127;
      float* sh = (float*)smu + h*128;
      const float* er = emb + (size_t)d_prev[bt]*H;
      int base = bid*8 + h*4;
#pragma unroll
      for (int j = 0; j < 4; j++) {
        int col = base + j;
        float e   = leaky(er[col]);
        float mu  = bredsum128(e, sh, bt) * (1.f/B);
        float dd  = e - mu;
        float var = bredsum128(dd*dd, sh, bt) * (1.f/B);
        d_six[bt*H + col] = bn2g[col]*dd*rsqrtf(var + EPS_BN) + bn2b[col];
      }
    }
    gsync();
    // ---- phase 2: three GRU-input GEMMs (all 144 blocks) ----
    {
      int z = bid / 48, nt = bid - z*48, n0 = nt*32;
      const float* A    = (z==0) ? d_six : (z==1) ? d_hx : d_hm;
      const float* W    = (z==0) ? gx_wih : (z==1) ? gx_whh : gm_whh;
      int ldw           = (z==0) ? 2*H : H;
      const float* bias = (z==0) ? (const float*)0 : (z==1) ? gx_bhh : gm_bhh;
      const float* addM = (z==0) ? d_cz : (const float*)0;
      float* Cm         = (z==0) ? d_gi : (z==1) ? d_ghx : d_ghm;
      gemm_phase<4>(A, W, ldw, bias, addM, H3, Cm, H3, n0,
                    (const float*)0, 1.f, smu);
    }
    gsync();
    // ---- phase 3: GRU + cosine gate + bn3 (64 blocks, 8 cols) ----
    if (bid < 64) {
      int h = tid >> 7, bt = tid & 127;
      float* sh = (float*)smu + h*128;
      int base = bid*8 + h*4;
      const float* gim = d_gim + s*H3;
      float hx2[4], hm2[4];
#pragma unroll
      for (int j = 0; j < 4; j++) {
        int col = base + j;
        float ir = d_gi [bt*H3+col], iz = d_gi [bt*H3+H+col], in_ = d_gi [bt*H3+2*H+col];
        float hr = d_ghx[bt*H3+col], hz = d_ghx[bt*H3+H+col], hn  = d_ghx[bt*H3+2*H+col];
        float hv = d_hx[bt*H+col];
        float r  = sig(ir+hr), zg = sig(iz+hz);
        float n  = tanhf(in_ + r*hn);
        hx2[j] = (1.f-zg)*n + zg*hv;
        float mir = gim[col], miz = gim[H+col], min_ = gim[2*H+col];
        float mhr = d_ghm[bt*H3+col], mhz = d_ghm[bt*H3+H+col], mhn = d_ghm[bt*H3+2*H+col];
        float hmv = d_hm[bt*H+col];
        float rm  = sig(mir+mhr), zm = sig(miz+mhz);
        float nm  = tanhf(min_ + rm*mhn);
        hm2[j] = (1.f-zm)*nm + zm*hmv;
        d_hx[bt*H+col] = hx2[j];
        d_hm[bt*H+col] = hm2[j];
      }
      float dot=0.f, na=0.f, nb2=0.f;
#pragma unroll
      for (int j = 0; j < 4; j++) { dot += hx2[j]*hm2[j]; na += hx2[j]*hx2[j]; nb2 += hm2[j]*hm2[j]; }
      float gate = dot / fmaxf(sqrtf(na)*sqrtf(nb2), EPS_COS);
#pragma unroll
      for (int j = 0; j < 4; j++) {
        int col = base + j;
        float o   = leaky(gate*hx2[j] + (1.f-gate)*hm2[j]);
        float mu  = bredsum128(o, sh, bt) * (1.f/B);
        float dd  = o - mu;
        float var = bredsum128(dd*dd, sh, bt) * (1.f/B);
        d_o[bt*H+col] = bn3g[col]*dd*rsqrtf(var + EPS_BN) + bn3b[col];
      }
    }
    gsync();
    // ---- phase 4: logits GEMM + (bias + gumbel)/T (128 blocks) ----
    if (bid < 128)
      gemm_phase<8>(d_o, h2o_w, H, h2o_b, (const float*)0, 0,
                    d_logits, V, bid*64, d_g + (size_t)s*BV, t, smu);
    gsync();
    // ---- phase 5: softmax + argmax + write probs (128 blocks) ----
    if (bid < 128) {
      float* se   = (float*)smu;            // 8192 floats
      float* red  = (float*)smu + 8192;     // 256
      int*   redi = (int*)((float*)smu + 8448);
      int b2 = bid;
      const float* row = d_logits + (size_t)b2*V;
      float m = -3.0e38f;
      for (int v = tid; v < V; v += 256) m = fmaxf(m, row[v]);
      red[tid] = m; __syncthreads();
#pragma unroll
      for (int o = 128; o > 0; o >>= 1) { if (tid < o) red[tid] = fmaxf(red[tid], red[tid+o]); __syncthreads(); }
      m = red[0]; __syncthreads();
      float sum = 0.f;
      for (int v = tid; v < V; v += 256) { float e = expf(row[v]-m); se[v] = e; sum += e; }
      red[tid] = sum; __syncthreads();
#pragma unroll
      for (int o = 128; o > 0; o >>= 1) { if (tid < o) red[tid] += red[tid+o]; __syncthreads(); }
      sum = red[0]; __syncthreads();
      float best = -1.f; int bi = 0;
      float* orow = out + (size_t)b2*S*V + (size_t)s*V;
      for (int v = tid; v < V; v += 256) {
        float p = se[v] / sum;
        orow[v] = p;
        if (p > best) { best = p; bi = v; }
      }
      red[tid] = best; redi[tid] = bi; __syncthreads();
#pragma unroll
      for (int o = 128; o > 0; o >>= 1) {
        if (tid < o) {
          float ov = red[tid+o]; int oi = redi[tid+o];
          if (ov > red[tid] || (ov == red[tid] && oi < redi[tid])) { red[tid] = ov; redi[tid] = oi; }
        }
        __syncthreads();
      }
      if (tid == 0) d_prev[b2] = redi[0];
    }
    gsync();
  }
}

// ---------------- launch ------------------------------------------------------
extern "C" void kernel_launch(void* const* d_in, const int* in_sizes, int n_in,
                              void* d_out, int out_size) {
  const float* z      = (const float*)d_in[0];
  const float* temp   = (const float*)d_in[1];
  const float* z2h_w  = (const float*)d_in[2];
  const float* z2h_b  = (const float*)d_in[3];
  const float* bn1_g  = (const float*)d_in[4];
  const float* bn1_b  = (const float*)d_in[5];
  const float* emb    = (const float*)d_in[6];
  const float* bn2_g  = (const float*)d_in[7];
  const float* bn2_b  = (const float*)d_in[8];
  const float* memory = (const float*)d_in[9];
  const float* gx_wih = (const float*)d_in[10];
  const float* gx_whh = (const float*)d_in[11];
  const float* gx_bih = (const float*)d_in[12];
  const float* gx_bhh = (const float*)d_in[13];
  const float* gm_wih = (const float*)d_in[14];
  const float* gm_whh = (const float*)d_in[15];
  const float* gm_bih = (const float*)d_in[16];
  const float* gm_bhh = (const float*)d_in[17];
  const float* bn3_g  = (const float*)d_in[18];
  const float* bn3_b  = (const float*)d_in[19];
  const float* h2o_w  = (const float*)d_in[20];
  const float* h2o_b  = (const float*)d_in[21];
  float* out = (float*)d_out;

  k_keys   <<<1, 64>>>();
  k_gumbel <<<(S*(size_t)BV)/256, 256>>>();
  k_z0     <<<128, 128>>>(z, z2h_w, z2h_b, bn1_g, bn1_b);
  k_prep   <<<256, 256>>>();
  k_siz    <<<128, 128>>>(bn2_g, bn2_b);
  k_cz     <<<48, 256>>>(gx_wih, gx_bih);
  k_gim    <<<S, 256>>>(memory, gm_wih, gm_bih);

  k_steps  <<<NB, 256>>>(emb, bn2_g, bn2_b,
                         gx_wih, gx_whh, gm_whh, gx_bhh, gm_bhh,
                         bn3_g, bn3_b, h2o_w, h2o_b, temp, out);
}